// round 7
// baseline (speedup 1.0000x reference)
#include <cuda_runtime.h>
#include <cuda_fp16.h>
#include <cstdint>
#include <math.h>

#define Dd    2048
#define NTOK  4096
#define Sq    1024
#define HDh   64
#define NBH   128
#define EPSV  1e-5f
#define INV_SQRT_D 0.022097086912079608f

// ---------------- scratch ---------------------------------------------------
__device__ float g_x2[(size_t)NTOK * Dd];
__device__ __half g_hh [(size_t)NTOK * Dd], g_hl [(size_t)NTOK * Dd];
__device__ __half g_h2h[(size_t)NTOK * Dd], g_h2l[(size_t)NTOK * Dd];
__device__ __half g_f1h[(size_t)NTOK * Dd], g_f1l[(size_t)NTOK * Dd];
__device__ __half g_qh [(size_t)NTOK * Dd], g_ql [(size_t)NTOK * Dd];
__device__ __half g_kh [(size_t)NTOK * Dd], g_kl [(size_t)NTOK * Dd];
__device__ __half g_wq[(size_t)Dd * Dd], g_wk[(size_t)Dd * Dd];
__device__ __half g_w1[(size_t)Dd * Dd], g_w2[(size_t)Dd * Dd];

// ---------------- helpers ----------------------------------------------------
__device__ __forceinline__ uint32_t smem_u32(const void* p) {
    return (uint32_t)__cvta_generic_to_shared(p);
}
__device__ __forceinline__ void cp16(uint32_t dst, const void* src) {
    asm volatile("cp.async.cg.shared.global [%0], [%1], 16;" :: "r"(dst), "l"(src));
}
__device__ __forceinline__ void cp_commit() {
    asm volatile("cp.async.commit_group;");
}
template<int N> __device__ __forceinline__ void cp_wait() {
    asm volatile("cp.async.wait_group %0;" :: "n"(N));
}
__device__ __forceinline__ void ldmx4(uint32_t a, uint32_t& r0, uint32_t& r1,
                                      uint32_t& r2, uint32_t& r3) {
    asm volatile("ldmatrix.sync.aligned.m8n8.x4.shared.b16 {%0,%1,%2,%3},[%4];"
                 : "=r"(r0), "=r"(r1), "=r"(r2), "=r"(r3) : "r"(a));
}
__device__ __forceinline__ void ldmx4t(uint32_t a, uint32_t& r0, uint32_t& r1,
                                       uint32_t& r2, uint32_t& r3) {
    asm volatile("ldmatrix.sync.aligned.m8n8.x4.trans.shared.b16 {%0,%1,%2,%3},[%4];"
                 : "=r"(r0), "=r"(r1), "=r"(r2), "=r"(r3) : "r"(a));
}
__device__ __forceinline__ void mma16816(float* c, const uint32_t* a, const uint32_t* b) {
    asm volatile(
        "mma.sync.aligned.m16n8k16.row.col.f32.f16.f16.f32 "
        "{%0,%1,%2,%3},{%4,%5,%6,%7},{%8,%9},{%0,%1,%2,%3};"
        : "+f"(c[0]), "+f"(c[1]), "+f"(c[2]), "+f"(c[3])
        : "r"(a[0]), "r"(a[1]), "r"(a[2]), "r"(a[3]), "r"(b[0]), "r"(b[1]));
}
__device__ __forceinline__ void split2h(float v0, float v1, __half2& hi, __half2& lo) {
    __half h0 = __float2half_rn(v0);
    __half h1 = __float2half_rn(v1);
    __half l0 = __float2half_rn(v0 - __half2float(h0));
    __half l1 = __float2half_rn(v1 - __half2float(h1));
    hi = __halves2half2(h0, h1);
    lo = __halves2half2(l0, l1);
}
__device__ __forceinline__ void split_store4h(__half* hi, __half* lo,
                                              size_t idx, float4 v) {
    __half2 h01, l01, h23, l23;
    split2h(v.x, v.y, h01, l01);
    split2h(v.z, v.w, h23, l23);
    *(__half2*)(hi + idx)     = h01;
    *(__half2*)(hi + idx + 2) = h23;
    *(__half2*)(lo + idx)     = l01;
    *(__half2*)(lo + idx + 2) = l23;
}

// ---------------- weight convert (fp32 -> fp16 single plane) -----------------
__global__ __launch_bounds__(256) void cvt_h(const float4* __restrict__ W,
                                             __half* __restrict__ o, int n4) {
    int i = blockIdx.x * 256 + threadIdx.x;
    if (i >= n4) return;
    float4 v = W[i];
    *(__half2*)(o + (size_t)i * 4)     = __floats2half2_rn(v.x, v.y);
    *(__half2*)(o + (size_t)i * 4 + 2) = __floats2half2_rn(v.z, v.w);
}

// ---------------- fused LN1 / residual / LN2 ---------------------------------
__global__ __launch_bounds__(256) void ln_fused(
    const float* __restrict__ x,
    const float* __restrict__ s1, const float* __restrict__ b1,
    const float* __restrict__ s2, const float* __restrict__ b2)
{
    __shared__ float rbuf[16];
    __shared__ float stats[2];
    const int tid = threadIdx.x;
    const size_t base = (size_t)blockIdx.x * Dd;
    const float4* xr = (const float4*)(x + base);
    float4 a0 = xr[tid];
    float4 a1 = xr[tid + 256];

    float s = a0.x + a0.y + a0.z + a0.w + a1.x + a1.y + a1.z + a1.w;
    float q = a0.x*a0.x + a0.y*a0.y + a0.z*a0.z + a0.w*a0.w
            + a1.x*a1.x + a1.y*a1.y + a1.z*a1.z + a1.w*a1.w;
    #pragma unroll
    for (int o = 16; o; o >>= 1) {
        s += __shfl_xor_sync(0xffffffffu, s, o);
        q += __shfl_xor_sync(0xffffffffu, q, o);
    }
    if ((tid & 31) == 0) { rbuf[tid >> 5] = s; rbuf[8 + (tid >> 5)] = q; }
    __syncthreads();
    if (tid == 0) {
        float ss = 0.f, qq = 0.f;
        #pragma unroll
        for (int i = 0; i < 8; i++) { ss += rbuf[i]; qq += rbuf[8 + i]; }
        float m = ss * (1.0f / Dd);
        stats[0] = m;
        stats[1] = rsqrtf(qq * (1.0f / Dd) - m * m + EPSV);
    }
    __syncthreads();
    float m = stats[0], r = stats[1];

    const float4* s1v = (const float4*)s1;
    const float4* b1v = (const float4*)b1;
    float4 sc0 = s1v[tid], sc1 = s1v[tid + 256];
    float4 bi0 = b1v[tid], bi1 = b1v[tid + 256];

    float4 h0, h1, x20, x21;
    h0.x = (a0.x - m) * r * sc0.x + bi0.x;  h0.y = (a0.y - m) * r * sc0.y + bi0.y;
    h0.z = (a0.z - m) * r * sc0.z + bi0.z;  h0.w = (a0.w - m) * r * sc0.w + bi0.w;
    h1.x = (a1.x - m) * r * sc1.x + bi1.x;  h1.y = (a1.y - m) * r * sc1.y + bi1.y;
    h1.z = (a1.z - m) * r * sc1.z + bi1.z;  h1.w = (a1.w - m) * r * sc1.w + bi1.w;
    x20.x = h0.x + a0.x; x20.y = h0.y + a0.y; x20.z = h0.z + a0.z; x20.w = h0.w + a0.w;
    x21.x = h1.x + a1.x; x21.y = h1.y + a1.y; x21.z = h1.z + a1.z; x21.w = h1.w + a1.w;

    split_store4h(g_hh, g_hl, base + (size_t)tid * 4, h0);
    split_store4h(g_hh, g_hl, base + (size_t)(tid + 256) * 4, h1);
    ((float4*)(g_x2 + base))[tid]       = x20;
    ((float4*)(g_x2 + base))[tid + 256] = x21;

    s = x20.x + x20.y + x20.z + x20.w + x21.x + x21.y + x21.z + x21.w;
    q = x20.x*x20.x + x20.y*x20.y + x20.z*x20.z + x20.w*x20.w
      + x21.x*x21.x + x21.y*x21.y + x21.z*x21.z + x21.w*x21.w;
    #pragma unroll
    for (int o = 16; o; o >>= 1) {
        s += __shfl_xor_sync(0xffffffffu, s, o);
        q += __shfl_xor_sync(0xffffffffu, q, o);
    }
    if ((tid & 31) == 0) { rbuf[tid >> 5] = s; rbuf[8 + (tid >> 5)] = q; }
    __syncthreads();
    if (tid == 0) {
        float ss = 0.f, qq = 0.f;
        #pragma unroll
        for (int i = 0; i < 8; i++) { ss += rbuf[i]; qq += rbuf[8 + i]; }
        float mm = ss * (1.0f / Dd);
        stats[0] = mm;
        stats[1] = rsqrtf(qq * (1.0f / Dd) - mm * mm + EPSV);
    }
    __syncthreads();
    m = stats[0]; r = stats[1];

    const float4* s2v = (const float4*)s2;
    const float4* b2v = (const float4*)b2;
    sc0 = s2v[tid]; sc1 = s2v[tid + 256];
    bi0 = b2v[tid]; bi1 = b2v[tid + 256];
    float4 o0, o1;
    o0.x = (x20.x - m) * r * sc0.x + bi0.x;  o0.y = (x20.y - m) * r * sc0.y + bi0.y;
    o0.z = (x20.z - m) * r * sc0.z + bi0.z;  o0.w = (x20.w - m) * r * sc0.w + bi0.w;
    o1.x = (x21.x - m) * r * sc1.x + bi1.x;  o1.y = (x21.y - m) * r * sc1.y + bi1.y;
    o1.z = (x21.z - m) * r * sc1.z + bi1.z;  o1.w = (x21.w - m) * r * sc1.w + bi1.w;
    split_store4h(g_h2h, g_h2l, base + (size_t)tid * 4, o0);
    split_store4h(g_h2h, g_h2l, base + (size_t)(tid + 256) * 4, o1);
}

// ---------------------------------------------------------------------------
// fp16 split-2 GEMM, high-occupancy: C = (Ah+Al) * B.
// Block tile 128x128, BK=32, 512 threads = 16 warps (4Mx4N), warp tile 32x32.
// ~32 acc regs/thread -> 1 CTA/SM = 16 warps (vs 8 before).
// EPI: 1 = relu(acc+bias) -> split fp16, 2 = acc+bias+addm -> fp32, 3 = split fp16
// ---------------------------------------------------------------------------
template<int EPI>
__global__ __launch_bounds__(512) void gemm2(
    int M, int N, int K,
    const __half* __restrict__ Ah, const __half* __restrict__ Al,
    const __half* __restrict__ Bm,
    float* __restrict__ C,
    const float* __restrict__ bias, const float* __restrict__ addm,
    __half* __restrict__ Ohi, __half* __restrict__ Olo)
{
    __shared__ __half sAh[128 * 40], sAl[128 * 40];
    __shared__ __half sB[32 * 136];

    const int tid = threadIdx.x;
    const int m0 = blockIdx.y * 128, n0 = blockIdx.x * 128;

    // 512 threads: one uint4 per plane each
    const __half* gAh = Ah + (size_t)(m0 + (tid >> 2)) * K + (tid & 3) * 8;
    const __half* gAl = Al + (size_t)(m0 + (tid >> 2)) * K + (tid & 3) * 8;
    const __half* gB  = Bm + (size_t)(tid >> 4) * N + n0 + (tid & 15) * 8;

    const int sa = (tid >> 2) * 40 + (tid & 3) * 8;
    const int sb = (tid >> 4) * 136 + (tid & 15) * 8;

    const int lane = tid & 31;
    const int wid = tid >> 5;
    const int wm = (wid >> 2) * 32;   // 4 M groups of 32 rows
    const int wn = (wid & 3) * 32;    // 4 N groups of 32 cols

    const uint32_t aBaseH = smem_u32(sAh) + (((wm + (lane & 15)) * 40 + ((lane >> 4) << 3)) << 1);
    const uint32_t aBaseL = smem_u32(sAl) + (((wm + (lane & 15)) * 40 + ((lane >> 4) << 3)) << 1);
    const uint32_t bBase  = smem_u32(sB)  + ((((lane & 15)) * 136 + wn + ((lane >> 4) << 3)) << 1);

    float acc[2][4][4];
    #pragma unroll
    for (int i = 0; i < 2; i++)
        #pragma unroll
        for (int j = 0; j < 4; j++)
            #pragma unroll
            for (int t = 0; t < 4; t++) acc[i][j][t] = 0.f;

    uint4 vah, val, vb;
    auto LDG = [&](int k0) {
        vah = *(const uint4*)(gAh + k0);
        val = *(const uint4*)(gAl + k0);
        vb  = *(const uint4*)(gB + (size_t)k0 * N);
    };
    auto STS = [&]() {
        *(uint4*)(sAh + sa) = vah;
        *(uint4*)(sAl + sa) = val;
        *(uint4*)(sB + sb)  = vb;
    };
    auto COMP = [&](int kb) {
        uint32_t afh[2][4], afl[2][4], bf[4][2];
        #pragma unroll
        for (int mt = 0; mt < 2; mt++) {
            ldmx4(aBaseH + ((mt * 16 * 40 + kb) << 1),
                  afh[mt][0], afh[mt][1], afh[mt][2], afh[mt][3]);
            ldmx4(aBaseL + ((mt * 16 * 40 + kb) << 1),
                  afl[mt][0], afl[mt][1], afl[mt][2], afl[mt][3]);
        }
        #pragma unroll
        for (int np = 0; np < 2; np++) {
            ldmx4t(bBase + ((kb * 136 + np * 16) << 1),
                   bf[2*np][0], bf[2*np][1], bf[2*np+1][0], bf[2*np+1][1]);
        }
        #pragma unroll
        for (int mt = 0; mt < 2; mt++)
            #pragma unroll
            for (int nt = 0; nt < 4; nt++) {
                mma16816(acc[mt][nt], afh[mt], bf[nt]);
                mma16816(acc[mt][nt], afl[mt], bf[nt]);
            }
    };

    LDG(0);
    STS();
    __syncthreads();
    for (int k0 = 32; k0 < K; k0 += 32) {
        LDG(k0);
        COMP(0);
        COMP(16);
        __syncthreads();
        STS();
        __syncthreads();
    }
    COMP(0);
    COMP(16);

    const int g = lane >> 2, tig = lane & 3;
    #pragma unroll
    for (int mt = 0; mt < 2; mt++) {
        #pragma unroll
        for (int nt = 0; nt < 4; nt++) {
            const int row = m0 + wm + mt * 16 + g;
            const int col = n0 + wn + nt * 8 + tig * 2;
            const float* a4 = acc[mt][nt];
            if (EPI == 3) {
                __half2 h01, l01, h23, l23;
                split2h(a4[0], a4[1], h01, l01);
                split2h(a4[2], a4[3], h23, l23);
                *(__half2*)(Ohi + (size_t)row * N + col)       = h01;
                *(__half2*)(Olo + (size_t)row * N + col)       = l01;
                *(__half2*)(Ohi + (size_t)(row + 8) * N + col) = h23;
                *(__half2*)(Olo + (size_t)(row + 8) * N + col) = l23;
            } else if (EPI == 1) {
                float b0 = bias[col], b1 = bias[col + 1];
                float v0 = fmaxf(a4[0] + b0, 0.f), v1 = fmaxf(a4[1] + b1, 0.f);
                float v2 = fmaxf(a4[2] + b0, 0.f), v3 = fmaxf(a4[3] + b1, 0.f);
                __half2 h01, l01, h23, l23;
                split2h(v0, v1, h01, l01);
                split2h(v2, v3, h23, l23);
                *(__half2*)(Ohi + (size_t)row * N + col)       = h01;
                *(__half2*)(Olo + (size_t)row * N + col)       = l01;
                *(__half2*)(Ohi + (size_t)(row + 8) * N + col) = h23;
                *(__half2*)(Olo + (size_t)(row + 8) * N + col) = l23;
            } else { // EPI == 2
                float b0 = bias[col], b1 = bias[col + 1];
                float2 ad0 = *(const float2*)(addm + (size_t)row * N + col);
                float2 ad1 = *(const float2*)(addm + (size_t)(row + 8) * N + col);
                *(float2*)(C + (size_t)row * N + col) =
                    make_float2(a4[0] + b0 + ad0.x, a4[1] + b1 + ad0.y);
                *(float2*)(C + (size_t)(row + 8) * N + col) =
                    make_float2(a4[2] + b0 + ad1.x, a4[3] + b1 + ad1.y);
            }
        }
    }
}

// -----------------------------------------------------------------------------
// Fused scores + softmax, register-resident scores (fp16, 3-term) — unchanged.
// -----------------------------------------------------------------------------
#define FS_QH   0u
#define FS_QL   2304u
#define FS_KH0  4608u
#define FS_KL0  41472u
#define FS_KSTR 73728u
#define FS_RED  152064u
#define FS_SMEM 153088u

__global__ __launch_bounds__(512) void scores_softmax(
    const __half* __restrict__ Qh, const __half* __restrict__ Ql,
    const __half* __restrict__ Kh, const __half* __restrict__ Kl,
    float* __restrict__ attn)
{
    extern __shared__ __align__(16) char dsm[];
    const uint32_t sbase = smem_u32(dsm);
    float* red = (float*)(dsm + FS_RED);

    const int tid = threadIdx.x;
    const int lane = tid & 31;
    const int wid = tid >> 5;
    const int bh = blockIdx.y;
    const int m0 = blockIdx.x * 16;
    const size_t off = (size_t)(bh >> 5) * ((size_t)Sq * Dd) + (size_t)(bh & 31) * HDh;

    if (tid < 256) {
        int plane = tid >> 7, i2 = tid & 127;
        int row = i2 >> 3, col = (i2 & 7) * 8;
        const __half* src = (plane ? Ql : Qh) + off + (size_t)(m0 + row) * Dd + col;
        cp16(sbase + (plane ? FS_QL : FS_QH) + (row * 72 + col) * 2, src);
    }
    auto ISSUEK = [&](int chunk, int buf) {
        #pragma unroll
        for (int p = 0; p < 8; p++) {
            int idx = tid + p * 512;
            int plane = idx >> 11;
            int i2 = idx & 2047;
            int row = i2 >> 3, col = (i2 & 7) * 8;
            const __half* src = (plane ? Kl : Kh) + off
                              + (size_t)(chunk * 256 + row) * Dd + col;
            cp16(sbase + (plane ? FS_KL0 : FS_KH0) + (uint32_t)buf * FS_KSTR
                 + (row * 72 + col) * 2, src);
        }
        cp_commit();
    };
    ISSUEK(0, 0);
    ISSUEK(1, 1);
    cp_wait<1>();
    __syncthreads();

    const uint32_t aOff = (((lane & 15)) * 72 + ((lane >> 4) << 3)) * 2;
    uint32_t afh[4][4], afl[4][4];
    #pragma unroll
    for (int kb4 = 0; kb4 < 4; kb4++) {
        ldmx4(sbase + FS_QH + aOff + ((kb4 * 16) << 1),
              afh[kb4][0], afh[kb4][1], afh[kb4][2], afh[kb4][3]);
        ldmx4(sbase + FS_QL + aOff + ((kb4 * 16) << 1),
              afl[kb4][0], afl[kb4][1], afl[kb4][2], afl[kb4][3]);
    }

    const int bRow = ((lane >> 4) << 3) + (lane & 7);
    const int bKof = ((lane >> 3) & 1) << 3;
    const uint32_t bOff = ((wid * 16 + bRow) * 72 + bKof) * 2;

    float acc[4][2][4];
    #pragma unroll
    for (int it = 0; it < 4; it++)
        #pragma unroll
        for (int nt = 0; nt < 2; nt++)
            #pragma unroll
            for (int t = 0; t < 4; t++) acc[it][nt][t] = 0.f;

    #pragma unroll
    for (int it = 0; it < 4; it++) {
        const int buf = it & 1;
        const uint32_t kh = sbase + FS_KH0 + (uint32_t)buf * FS_KSTR + bOff;
        const uint32_t kl = sbase + FS_KL0 + (uint32_t)buf * FS_KSTR + bOff;
        #pragma unroll
        for (int kb4 = 0; kb4 < 4; kb4++) {
            uint32_t bh4[4], bl4[4];
            ldmx4(kh + ((kb4 * 16) << 1), bh4[0], bh4[1], bh4[2], bh4[3]);
            ldmx4(kl + ((kb4 * 16) << 1), bl4[0], bl4[1], bl4[2], bl4[3]);
            #pragma unroll
            for (int nt = 0; nt < 2; nt++) {
                mma16816(acc[it][nt], afh[kb4], &bh4[nt * 2]);
                mma16816(acc[it][nt], afh[kb4], &bl4[nt * 2]);
                mma16816(acc[it][nt], afl[kb4], &bh4[nt * 2]);
            }
        }
        if (it < 2) {
            __syncthreads();
            ISSUEK(it + 2, buf);
            cp_wait<1>();
            __syncthreads();
        } else if (it == 2) {
            cp_wait<0>();
            __syncthreads();
        }
    }

    const int g = lane >> 2, tig = lane & 3;
    const float c = INV_SQRT_D;
    float mx0 = -1e30f, mx1 = -1e30f;
    #pragma unroll
    for (int it = 0; it < 4; it++)
        #pragma unroll
        for (int nt = 0; nt < 2; nt++) {
            float* a4 = acc[it][nt];
            a4[0] *= c; a4[1] *= c; a4[2] *= c; a4[3] *= c;
            mx0 = fmaxf(mx0, fmaxf(a4[0], a4[1]));
            mx1 = fmaxf(mx1, fmaxf(a4[2], a4[3]));
        }
    mx0 = fmaxf(mx0, __shfl_xor_sync(0xffffffffu, mx0, 1));
    mx0 = fmaxf(mx0, __shfl_xor_sync(0xffffffffu, mx0, 2));
    mx1 = fmaxf(mx1, __shfl_xor_sync(0xffffffffu, mx1, 1));
    mx1 = fmaxf(mx1, __shfl_xor_sync(0xffffffffu, mx1, 2));
    if (tig == 0) { red[g * 16 + wid] = mx0; red[(g + 8) * 16 + wid] = mx1; }
    __syncthreads();
    float m0f = -1e30f, m1f = -1e30f;
    #pragma unroll
    for (int w = 0; w < 16; w++) {
        m0f = fmaxf(m0f, red[g * 16 + w]);
        m1f = fmaxf(m1f, red[(g + 8) * 16 + w]);
    }
    __syncthreads();

    float s0 = 0.f, s1 = 0.f;
    #pragma unroll
    for (int it = 0; it < 4; it++)
        #pragma unroll
        for (int nt = 0; nt < 2; nt++) {
            float* a4 = acc[it][nt];
            a4[0] = __expf(a4[0] - m0f); a4[1] = __expf(a4[1] - m0f);
            a4[2] = __expf(a4[2] - m1f); a4[3] = __expf(a4[3] - m1f);
            s0 += a4[0] + a4[1];
            s1 += a4[2] + a4[3];
        }
    s0 += __shfl_xor_sync(0xffffffffu, s0, 1);
    s0 += __shfl_xor_sync(0xffffffffu, s0, 2);
    s1 += __shfl_xor_sync(0xffffffffu, s1, 1);
    s1 += __shfl_xor_sync(0xffffffffu, s1, 2);
    if (tig == 0) { red[g * 16 + wid] = s0; red[(g + 8) * 16 + wid] = s1; }
    __syncthreads();
    float t0 = 0.f, t1 = 0.f;
    #pragma unroll
    for (int w = 0; w < 16; w++) {
        t0 += red[g * 16 + w];
        t1 += red[(g + 8) * 16 + w];
    }
    const float inv0 = __fdividef(1.0f, t0);
    const float inv1 = __fdividef(1.0f, t1);

    float* base0 = attn + (size_t)bh * Sq * Sq + (size_t)(m0 + g) * Sq;
    float* base1 = base0 + (size_t)8 * Sq;
    #pragma unroll
    for (int it = 0; it < 4; it++)
        #pragma unroll
        for (int nt = 0; nt < 2; nt++) {
            const int col = it * 256 + wid * 16 + nt * 8 + tig * 2;
            const float* a4 = acc[it][nt];
            *(float2*)(base0 + col) = make_float2(a4[0] * inv0, a4[1] * inv0);
            *(float2*)(base1 + col) = make_float2(a4[2] * inv1, a4[3] * inv1);
        }
}

// -----------------------------------------------------------------------------
extern "C" void kernel_launch(void* const* d_in, const int* in_sizes, int n_in,
                              void* d_out, int out_size)
{
    (void)in_sizes; (void)n_in; (void)out_size;
    const float* x    = (const float*)d_in[0];
    const float* Wq   = (const float*)d_in[1];
    const float* Wk   = (const float*)d_in[2];
    /* d_in[3] = Wv : dead in the reference */
    const float* ln1s = (const float*)d_in[4];
    const float* ln1b = (const float*)d_in[5];
    const float* ln2s = (const float*)d_in[6];
    const float* ln2b = (const float*)d_in[7];
    const float* ff1w = (const float*)d_in[8];
    const float* ff1b = (const float*)d_in[9];
    const float* ff2w = (const float*)d_in[10];
    const float* ff2b = (const float*)d_in[11];

    float* out  = (float*)d_out;
    float* attn = out + (size_t)NTOK * Dd;

    float* px2;
    __half *phh, *phl, *ph2h, *ph2l, *pf1h, *pf1l, *pqh, *pql, *pkh, *pkl;
    __half *pwq, *pwk, *pw1, *pw2;
    cudaGetSymbolAddress((void**)&px2,  g_x2);
    cudaGetSymbolAddress((void**)&phh,  g_hh);
    cudaGetSymbolAddress((void**)&phl,  g_hl);
    cudaGetSymbolAddress((void**)&ph2h, g_h2h);
    cudaGetSymbolAddress((void**)&ph2l, g_h2l);
    cudaGetSymbolAddress((void**)&pf1h, g_f1h);
    cudaGetSymbolAddress((void**)&pf1l, g_f1l);
    cudaGetSymbolAddress((void**)&pqh,  g_qh);
    cudaGetSymbolAddress((void**)&pql,  g_ql);
    cudaGetSymbolAddress((void**)&pkh,  g_kh);
    cudaGetSymbolAddress((void**)&pkl,  g_kl);
    cudaGetSymbolAddress((void**)&pwq,  g_wq);
    cudaGetSymbolAddress((void**)&pwk,  g_wk);
    cudaGetSymbolAddress((void**)&pw1,  g_w1);
    cudaGetSymbolAddress((void**)&pw2,  g_w2);

    cudaFuncSetAttribute(scores_softmax, cudaFuncAttributeMaxDynamicSharedMemorySize, FS_SMEM);

    const int n4 = Dd * Dd / 4;
    cvt_h<<<(n4 + 255) / 256, 256>>>((const float4*)Wq,   pwq, n4);
    cvt_h<<<(n4 + 255) / 256, 256>>>((const float4*)Wk,   pwk, n4);
    cvt_h<<<(n4 + 255) / 256, 256>>>((const float4*)ff1w, pw1, n4);
    cvt_h<<<(n4 + 255) / 256, 256>>>((const float4*)ff2w, pw2, n4);

    ln_fused<<<NTOK, 256>>>(x, ln1s, ln1b, ln2s, ln2b);

    dim3 g0(Dd / 128, NTOK / 128);
    gemm2<3><<<g0, 512>>>(NTOK, Dd, Dd, phh, phl, pwq,
                          nullptr, nullptr, nullptr, pqh, pql);
    gemm2<3><<<g0, 512>>>(NTOK, Dd, Dd, phh, phl, pwk,
                          nullptr, nullptr, nullptr, pkh, pkl);
    gemm2<1><<<g0, 512>>>(NTOK, Dd, Dd, ph2h, ph2l, pw1,
                          nullptr, ff1b, nullptr, pf1h, pf1l);
    gemm2<2><<<g0, 512>>>(NTOK, Dd, Dd, pf1h, pf1l, pw2,
                          out, ff2b, px2, nullptr, nullptr);

    dim3 gs(Sq / 16, NBH);
    scores_softmax<<<gs, 512, FS_SMEM>>>(pqh, pql, pkh, pkl, attn);
}

// round 8
// speedup vs baseline: 1.0139x; 1.0139x over previous
#include <cuda_runtime.h>
#include <cuda_fp16.h>
#include <cstdint>
#include <math.h>

#define Dd    2048
#define NTOK  4096
#define Sq    1024
#define HDh   64
#define NBH   128
#define EPSV  1e-5f
#define INV_SQRT_D 0.022097086912079608f

// ---------------- scratch ---------------------------------------------------
__device__ float g_x2[(size_t)NTOK * Dd];
__device__ __half g_hh [(size_t)NTOK * Dd], g_hl [(size_t)NTOK * Dd];
__device__ __half g_h2h[(size_t)NTOK * Dd], g_h2l[(size_t)NTOK * Dd];
__device__ __half g_f1h[(size_t)NTOK * Dd], g_f1l[(size_t)NTOK * Dd];
__device__ __half g_qh [(size_t)NTOK * Dd], g_ql [(size_t)NTOK * Dd];
__device__ __half g_kh [(size_t)NTOK * Dd], g_kl [(size_t)NTOK * Dd];
__device__ __half g_wq[(size_t)Dd * Dd], g_wk[(size_t)Dd * Dd];
__device__ __half g_w1[(size_t)Dd * Dd], g_w2[(size_t)Dd * Dd];

// ---------------- helpers ----------------------------------------------------
__device__ __forceinline__ uint32_t smem_u32(const void* p) {
    return (uint32_t)__cvta_generic_to_shared(p);
}
__device__ __forceinline__ void cp16(uint32_t dst, const void* src) {
    asm volatile("cp.async.cg.shared.global [%0], [%1], 16;" :: "r"(dst), "l"(src));
}
__device__ __forceinline__ void cp_commit() {
    asm volatile("cp.async.commit_group;");
}
template<int N> __device__ __forceinline__ void cp_wait() {
    asm volatile("cp.async.wait_group %0;" :: "n"(N));
}
__device__ __forceinline__ void ldmx4(uint32_t a, uint32_t& r0, uint32_t& r1,
                                      uint32_t& r2, uint32_t& r3) {
    asm volatile("ldmatrix.sync.aligned.m8n8.x4.shared.b16 {%0,%1,%2,%3},[%4];"
                 : "=r"(r0), "=r"(r1), "=r"(r2), "=r"(r3) : "r"(a));
}
__device__ __forceinline__ void ldmx4t(uint32_t a, uint32_t& r0, uint32_t& r1,
                                       uint32_t& r2, uint32_t& r3) {
    asm volatile("ldmatrix.sync.aligned.m8n8.x4.trans.shared.b16 {%0,%1,%2,%3},[%4];"
                 : "=r"(r0), "=r"(r1), "=r"(r2), "=r"(r3) : "r"(a));
}
__device__ __forceinline__ void mma16816(float* c, const uint32_t* a, const uint32_t* b) {
    asm volatile(
        "mma.sync.aligned.m16n8k16.row.col.f32.f16.f16.f32 "
        "{%0,%1,%2,%3},{%4,%5,%6,%7},{%8,%9},{%0,%1,%2,%3};"
        : "+f"(c[0]), "+f"(c[1]), "+f"(c[2]), "+f"(c[3])
        : "r"(a[0]), "r"(a[1]), "r"(a[2]), "r"(a[3]), "r"(b[0]), "r"(b[1]));
}
__device__ __forceinline__ void split2h(float v0, float v1, __half2& hi, __half2& lo) {
    __half h0 = __float2half_rn(v0);
    __half h1 = __float2half_rn(v1);
    __half l0 = __float2half_rn(v0 - __half2float(h0));
    __half l1 = __float2half_rn(v1 - __half2float(h1));
    hi = __halves2half2(h0, h1);
    lo = __halves2half2(l0, l1);
}
__device__ __forceinline__ void split_store4h(__half* hi, __half* lo,
                                              size_t idx, float4 v) {
    __half2 h01, l01, h23, l23;
    split2h(v.x, v.y, h01, l01);
    split2h(v.z, v.w, h23, l23);
    *(__half2*)(hi + idx)     = h01;
    *(__half2*)(hi + idx + 2) = h23;
    *(__half2*)(lo + idx)     = l01;
    *(__half2*)(lo + idx + 2) = l23;
}

// ---------------- all-weights convert (one launch) ----------------------------
struct CvtArgs {
    const float4* w[4];
    __half* o[4];
};
__global__ __launch_bounds__(256) void cvt_all(CvtArgs a, int n4) {
    const int z = blockIdx.y;
    const float4* W = a.w[z];
    __half* o = a.o[z];
    int i = blockIdx.x * 256 + threadIdx.x;
    if (i >= n4) return;
    float4 v = W[i];
    *(__half2*)(o + (size_t)i * 4)     = __floats2half2_rn(v.x, v.y);
    *(__half2*)(o + (size_t)i * 4 + 2) = __floats2half2_rn(v.z, v.w);
}

// ---------------- fused LN1 / residual / LN2 ---------------------------------
__global__ __launch_bounds__(256) void ln_fused(
    const float* __restrict__ x,
    const float* __restrict__ s1, const float* __restrict__ b1,
    const float* __restrict__ s2, const float* __restrict__ b2)
{
    __shared__ float rbuf[16];
    __shared__ float stats[2];
    const int tid = threadIdx.x;
    const size_t base = (size_t)blockIdx.x * Dd;
    const float4* xr = (const float4*)(x + base);
    float4 a0 = xr[tid];
    float4 a1 = xr[tid + 256];

    float s = a0.x + a0.y + a0.z + a0.w + a1.x + a1.y + a1.z + a1.w;
    float q = a0.x*a0.x + a0.y*a0.y + a0.z*a0.z + a0.w*a0.w
            + a1.x*a1.x + a1.y*a1.y + a1.z*a1.z + a1.w*a1.w;
    #pragma unroll
    for (int o = 16; o; o >>= 1) {
        s += __shfl_xor_sync(0xffffffffu, s, o);
        q += __shfl_xor_sync(0xffffffffu, q, o);
    }
    if ((tid & 31) == 0) { rbuf[tid >> 5] = s; rbuf[8 + (tid >> 5)] = q; }
    __syncthreads();
    if (tid == 0) {
        float ss = 0.f, qq = 0.f;
        #pragma unroll
        for (int i = 0; i < 8; i++) { ss += rbuf[i]; qq += rbuf[8 + i]; }
        float m = ss * (1.0f / Dd);
        stats[0] = m;
        stats[1] = rsqrtf(qq * (1.0f / Dd) - m * m + EPSV);
    }
    __syncthreads();
    float m = stats[0], r = stats[1];

    const float4* s1v = (const float4*)s1;
    const float4* b1v = (const float4*)b1;
    float4 sc0 = s1v[tid], sc1 = s1v[tid + 256];
    float4 bi0 = b1v[tid], bi1 = b1v[tid + 256];

    float4 h0, h1, x20, x21;
    h0.x = (a0.x - m) * r * sc0.x + bi0.x;  h0.y = (a0.y - m) * r * sc0.y + bi0.y;
    h0.z = (a0.z - m) * r * sc0.z + bi0.z;  h0.w = (a0.w - m) * r * sc0.w + bi0.w;
    h1.x = (a1.x - m) * r * sc1.x + bi1.x;  h1.y = (a1.y - m) * r * sc1.y + bi1.y;
    h1.z = (a1.z - m) * r * sc1.z + bi1.z;  h1.w = (a1.w - m) * r * sc1.w + bi1.w;
    x20.x = h0.x + a0.x; x20.y = h0.y + a0.y; x20.z = h0.z + a0.z; x20.w = h0.w + a0.w;
    x21.x = h1.x + a1.x; x21.y = h1.y + a1.y; x21.z = h1.z + a1.z; x21.w = h1.w + a1.w;

    split_store4h(g_hh, g_hl, base + (size_t)tid * 4, h0);
    split_store4h(g_hh, g_hl, base + (size_t)(tid + 256) * 4, h1);
    ((float4*)(g_x2 + base))[tid]       = x20;
    ((float4*)(g_x2 + base))[tid + 256] = x21;

    s = x20.x + x20.y + x20.z + x20.w + x21.x + x21.y + x21.z + x21.w;
    q = x20.x*x20.x + x20.y*x20.y + x20.z*x20.z + x20.w*x20.w
      + x21.x*x21.x + x21.y*x21.y + x21.z*x21.z + x21.w*x21.w;
    #pragma unroll
    for (int o = 16; o; o >>= 1) {
        s += __shfl_xor_sync(0xffffffffu, s, o);
        q += __shfl_xor_sync(0xffffffffu, q, o);
    }
    if ((tid & 31) == 0) { rbuf[tid >> 5] = s; rbuf[8 + (tid >> 5)] = q; }
    __syncthreads();
    if (tid == 0) {
        float ss = 0.f, qq = 0.f;
        #pragma unroll
        for (int i = 0; i < 8; i++) { ss += rbuf[i]; qq += rbuf[8 + i]; }
        float mm = ss * (1.0f / Dd);
        stats[0] = mm;
        stats[1] = rsqrtf(qq * (1.0f / Dd) - mm * mm + EPSV);
    }
    __syncthreads();
    m = stats[0]; r = stats[1];

    const float4* s2v = (const float4*)s2;
    const float4* b2v = (const float4*)b2;
    sc0 = s2v[tid]; sc1 = s2v[tid + 256];
    bi0 = b2v[tid]; bi1 = b2v[tid + 256];
    float4 o0, o1;
    o0.x = (x20.x - m) * r * sc0.x + bi0.x;  o0.y = (x20.y - m) * r * sc0.y + bi0.y;
    o0.z = (x20.z - m) * r * sc0.z + bi0.z;  o0.w = (x20.w - m) * r * sc0.w + bi0.w;
    o1.x = (x21.x - m) * r * sc1.x + bi1.x;  o1.y = (x21.y - m) * r * sc1.y + bi1.y;
    o1.z = (x21.z - m) * r * sc1.z + bi1.z;  o1.w = (x21.w - m) * r * sc1.w + bi1.w;
    split_store4h(g_h2h, g_h2l, base + (size_t)tid * 4, o0);
    split_store4h(g_h2h, g_h2l, base + (size_t)(tid + 256) * 4, o1);
}

// ---------------------------------------------------------------------------
// fp16 split-2 GEMM (R6 body, 256 threads — best measured).
// DUAL=true: blockIdx.z selects weight/output pair (batched q+k projection).
// EPI: 1 = relu(acc+bias) -> split fp16, 2 = acc+bias+addm -> fp32, 3 = split fp16
// ---------------------------------------------------------------------------
template<int EPI, bool DUAL>
__global__ __launch_bounds__(256) void gemm2(
    int M, int N, int K,
    const __half* __restrict__ Ah, const __half* __restrict__ Al,
    const __half* __restrict__ Bm, const __half* __restrict__ Bm2,
    float* __restrict__ C,
    const float* __restrict__ bias, const float* __restrict__ addm,
    __half* __restrict__ Ohi, __half* __restrict__ Olo,
    __half* __restrict__ Ohi2, __half* __restrict__ Olo2)
{
    __shared__ __half sAh[128 * 40], sAl[128 * 40];
    __shared__ __half sB[32 * 136];

    const __half* Bsel = Bm;
    __half* OhiSel = Ohi;
    __half* OloSel = Olo;
    if (DUAL && blockIdx.z == 1) { Bsel = Bm2; OhiSel = Ohi2; OloSel = Olo2; }

    const int tid = threadIdx.x;
    const int m0 = blockIdx.y * 128, n0 = blockIdx.x * 128;
    const int s0 = tid, s1 = tid + 256;

    const __half* gAh0 = Ah + (size_t)(m0 + (s0 >> 2)) * K + (s0 & 3) * 8;
    const __half* gAh1 = Ah + (size_t)(m0 + (s1 >> 2)) * K + (s1 & 3) * 8;
    const __half* gAl0 = Al + (size_t)(m0 + (s0 >> 2)) * K + (s0 & 3) * 8;
    const __half* gAl1 = Al + (size_t)(m0 + (s1 >> 2)) * K + (s1 & 3) * 8;
    const __half* gB0  = Bsel + (size_t)(s0 >> 4) * N + n0 + (s0 & 15) * 8;
    const __half* gB1  = Bsel + (size_t)(s1 >> 4) * N + n0 + (s1 & 15) * 8;

    const int sa0 = (s0 >> 2) * 40 + (s0 & 3) * 8;
    const int sa1 = (s1 >> 2) * 40 + (s1 & 3) * 8;
    const int sb0 = (s0 >> 4) * 136 + (s0 & 15) * 8;
    const int sb1 = (s1 >> 4) * 136 + (s1 & 15) * 8;

    const int lane = tid & 31;
    const int wid = tid >> 5;
    const int wm = (wid & 1) * 64;
    const int wn = (wid >> 1) * 32;

    const uint32_t aBaseH = smem_u32(sAh) + (((wm + (lane & 15)) * 40 + ((lane >> 4) << 3)) << 1);
    const uint32_t aBaseL = smem_u32(sAl) + (((wm + (lane & 15)) * 40 + ((lane >> 4) << 3)) << 1);
    const uint32_t bBase  = smem_u32(sB)  + ((((lane & 15)) * 136 + wn + ((lane >> 4) << 3)) << 1);

    float acc[4][4][4];
    #pragma unroll
    for (int i = 0; i < 4; i++)
        #pragma unroll
        for (int j = 0; j < 4; j++)
            #pragma unroll
            for (int t = 0; t < 4; t++) acc[i][j][t] = 0.f;

    uint4 vah0, vah1, val0, val1, vb0, vb1;
    auto LDG = [&](int k0) {
        vah0 = *(const uint4*)(gAh0 + k0);
        vah1 = *(const uint4*)(gAh1 + k0);
        val0 = *(const uint4*)(gAl0 + k0);
        val1 = *(const uint4*)(gAl1 + k0);
        vb0  = *(const uint4*)(gB0 + (size_t)k0 * N);
        vb1  = *(const uint4*)(gB1 + (size_t)k0 * N);
    };
    auto STS = [&]() {
        *(uint4*)(sAh + sa0) = vah0;  *(uint4*)(sAh + sa1) = vah1;
        *(uint4*)(sAl + sa0) = val0;  *(uint4*)(sAl + sa1) = val1;
        *(uint4*)(sB + sb0) = vb0;    *(uint4*)(sB + sb1) = vb1;
    };
    auto COMP = [&](int kb) {
        uint32_t afh[4][4], afl[4][4], bf[4][2];
        #pragma unroll
        for (int mt = 0; mt < 4; mt++) {
            ldmx4(aBaseH + ((mt * 16 * 40 + kb) << 1),
                  afh[mt][0], afh[mt][1], afh[mt][2], afh[mt][3]);
            ldmx4(aBaseL + ((mt * 16 * 40 + kb) << 1),
                  afl[mt][0], afl[mt][1], afl[mt][2], afl[mt][3]);
        }
        #pragma unroll
        for (int np = 0; np < 2; np++) {
            ldmx4t(bBase + ((kb * 136 + np * 16) << 1),
                   bf[2*np][0], bf[2*np][1], bf[2*np+1][0], bf[2*np+1][1]);
        }
        #pragma unroll
        for (int mt = 0; mt < 4; mt++)
            #pragma unroll
            for (int nt = 0; nt < 4; nt++) {
                mma16816(acc[mt][nt], afh[mt], bf[nt]);
                mma16816(acc[mt][nt], afl[mt], bf[nt]);
            }
    };

    LDG(0);
    STS();
    __syncthreads();
    for (int k0 = 32; k0 < K; k0 += 32) {
        LDG(k0);
        COMP(0);
        COMP(16);
        __syncthreads();
        STS();
        __syncthreads();
    }
    COMP(0);
    COMP(16);

    const int g = lane >> 2, tig = lane & 3;
    #pragma unroll
    for (int mt = 0; mt < 4; mt++) {
        #pragma unroll
        for (int nt = 0; nt < 4; nt++) {
            const int row = m0 + wm + mt * 16 + g;
            const int col = n0 + wn + nt * 8 + tig * 2;
            const float* a4 = acc[mt][nt];
            if (EPI == 3) {
                __half2 h01, l01, h23, l23;
                split2h(a4[0], a4[1], h01, l01);
                split2h(a4[2], a4[3], h23, l23);
                *(__half2*)(OhiSel + (size_t)row * N + col)       = h01;
                *(__half2*)(OloSel + (size_t)row * N + col)       = l01;
                *(__half2*)(OhiSel + (size_t)(row + 8) * N + col) = h23;
                *(__half2*)(OloSel + (size_t)(row + 8) * N + col) = l23;
            } else if (EPI == 1) {
                float b0 = bias[col], b1 = bias[col + 1];
                float v0 = fmaxf(a4[0] + b0, 0.f), v1 = fmaxf(a4[1] + b1, 0.f);
                float v2 = fmaxf(a4[2] + b0, 0.f), v3 = fmaxf(a4[3] + b1, 0.f);
                __half2 h01, l01, h23, l23;
                split2h(v0, v1, h01, l01);
                split2h(v2, v3, h23, l23);
                *(__half2*)(OhiSel + (size_t)row * N + col)       = h01;
                *(__half2*)(OloSel + (size_t)row * N + col)       = l01;
                *(__half2*)(OhiSel + (size_t)(row + 8) * N + col) = h23;
                *(__half2*)(OloSel + (size_t)(row + 8) * N + col) = l23;
            } else { // EPI == 2
                float b0 = bias[col], b1 = bias[col + 1];
                float2 ad0 = *(const float2*)(addm + (size_t)row * N + col);
                float2 ad1 = *(const float2*)(addm + (size_t)(row + 8) * N + col);
                *(float2*)(C + (size_t)row * N + col) =
                    make_float2(a4[0] + b0 + ad0.x, a4[1] + b1 + ad0.y);
                *(float2*)(C + (size_t)(row + 8) * N + col) =
                    make_float2(a4[2] + b0 + ad1.x, a4[3] + b1 + ad1.y);
            }
        }
    }
}

// -----------------------------------------------------------------------------
// Fused scores + softmax (unchanged from R6; placed at launch index 3 for ncu).
// -----------------------------------------------------------------------------
#define FS_QH   0u
#define FS_QL   2304u
#define FS_KH0  4608u
#define FS_KL0  41472u
#define FS_KSTR 73728u
#define FS_RED  152064u
#define FS_SMEM 153088u

__global__ __launch_bounds__(512) void scores_softmax(
    const __half* __restrict__ Qh, const __half* __restrict__ Ql,
    const __half* __restrict__ Kh, const __half* __restrict__ Kl,
    float* __restrict__ attn)
{
    extern __shared__ __align__(16) char dsm[];
    const uint32_t sbase = smem_u32(dsm);
    float* red = (float*)(dsm + FS_RED);

    const int tid = threadIdx.x;
    const int lane = tid & 31;
    const int wid = tid >> 5;
    const int bh = blockIdx.y;
    const int m0 = blockIdx.x * 16;
    const size_t off = (size_t)(bh >> 5) * ((size_t)Sq * Dd) + (size_t)(bh & 31) * HDh;

    if (tid < 256) {
        int plane = tid >> 7, i2 = tid & 127;
        int row = i2 >> 3, col = (i2 & 7) * 8;
        const __half* src = (plane ? Ql : Qh) + off + (size_t)(m0 + row) * Dd + col;
        cp16(sbase + (plane ? FS_QL : FS_QH) + (row * 72 + col) * 2, src);
    }
    auto ISSUEK = [&](int chunk, int buf) {
        #pragma unroll
        for (int p = 0; p < 8; p++) {
            int idx = tid + p * 512;
            int plane = idx >> 11;
            int i2 = idx & 2047;
            int row = i2 >> 3, col = (i2 & 7) * 8;
            const __half* src = (plane ? Kl : Kh) + off
                              + (size_t)(chunk * 256 + row) * Dd + col;
            cp16(sbase + (plane ? FS_KL0 : FS_KH0) + (uint32_t)buf * FS_KSTR
                 + (row * 72 + col) * 2, src);
        }
        cp_commit();
    };
    ISSUEK(0, 0);
    ISSUEK(1, 1);
    cp_wait<1>();
    __syncthreads();

    const uint32_t aOff = (((lane & 15)) * 72 + ((lane >> 4) << 3)) * 2;
    uint32_t afh[4][4], afl[4][4];
    #pragma unroll
    for (int kb4 = 0; kb4 < 4; kb4++) {
        ldmx4(sbase + FS_QH + aOff + ((kb4 * 16) << 1),
              afh[kb4][0], afh[kb4][1], afh[kb4][2], afh[kb4][3]);
        ldmx4(sbase + FS_QL + aOff + ((kb4 * 16) << 1),
              afl[kb4][0], afl[kb4][1], afl[kb4][2], afl[kb4][3]);
    }

    const int bRow = ((lane >> 4) << 3) + (lane & 7);
    const int bKof = ((lane >> 3) & 1) << 3;
    const uint32_t bOff = ((wid * 16 + bRow) * 72 + bKof) * 2;

    float acc[4][2][4];
    #pragma unroll
    for (int it = 0; it < 4; it++)
        #pragma unroll
        for (int nt = 0; nt < 2; nt++)
            #pragma unroll
            for (int t = 0; t < 4; t++) acc[it][nt][t] = 0.f;

    #pragma unroll
    for (int it = 0; it < 4; it++) {
        const int buf = it & 1;
        const uint32_t kh = sbase + FS_KH0 + (uint32_t)buf * FS_KSTR + bOff;
        const uint32_t kl = sbase + FS_KL0 + (uint32_t)buf * FS_KSTR + bOff;
        #pragma unroll
        for (int kb4 = 0; kb4 < 4; kb4++) {
            uint32_t bh4[4], bl4[4];
            ldmx4(kh + ((kb4 * 16) << 1), bh4[0], bh4[1], bh4[2], bh4[3]);
            ldmx4(kl + ((kb4 * 16) << 1), bl4[0], bl4[1], bl4[2], bl4[3]);
            #pragma unroll
            for (int nt = 0; nt < 2; nt++) {
                mma16816(acc[it][nt], afh[kb4], &bh4[nt * 2]);
                mma16816(acc[it][nt], afh[kb4], &bl4[nt * 2]);
                mma16816(acc[it][nt], afl[kb4], &bh4[nt * 2]);
            }
        }
        if (it < 2) {
            __syncthreads();
            ISSUEK(it + 2, buf);
            cp_wait<1>();
            __syncthreads();
        } else if (it == 2) {
            cp_wait<0>();
            __syncthreads();
        }
    }

    const int g = lane >> 2, tig = lane & 3;
    const float c = INV_SQRT_D;
    float mx0 = -1e30f, mx1 = -1e30f;
    #pragma unroll
    for (int it = 0; it < 4; it++)
        #pragma unroll
        for (int nt = 0; nt < 2; nt++) {
            float* a4 = acc[it][nt];
            a4[0] *= c; a4[1] *= c; a4[2] *= c; a4[3] *= c;
            mx0 = fmaxf(mx0, fmaxf(a4[0], a4[1]));
            mx1 = fmaxf(mx1, fmaxf(a4[2], a4[3]));
        }
    mx0 = fmaxf(mx0, __shfl_xor_sync(0xffffffffu, mx0, 1));
    mx0 = fmaxf(mx0, __shfl_xor_sync(0xffffffffu, mx0, 2));
    mx1 = fmaxf(mx1, __shfl_xor_sync(0xffffffffu, mx1, 1));
    mx1 = fmaxf(mx1, __shfl_xor_sync(0xffffffffu, mx1, 2));
    if (tig == 0) { red[g * 16 + wid] = mx0; red[(g + 8) * 16 + wid] = mx1; }
    __syncthreads();
    float m0f = -1e30f, m1f = -1e30f;
    #pragma unroll
    for (int w = 0; w < 16; w++) {
        m0f = fmaxf(m0f, red[g * 16 + w]);
        m1f = fmaxf(m1f, red[(g + 8) * 16 + w]);
    }
    __syncthreads();

    float s0 = 0.f, s1 = 0.f;
    #pragma unroll
    for (int it = 0; it < 4; it++)
        #pragma unroll
        for (int nt = 0; nt < 2; nt++) {
            float* a4 = acc[it][nt];
            a4[0] = __expf(a4[0] - m0f); a4[1] = __expf(a4[1] - m0f);
            a4[2] = __expf(a4[2] - m1f); a4[3] = __expf(a4[3] - m1f);
            s0 += a4[0] + a4[1];
            s1 += a4[2] + a4[3];
        }
    s0 += __shfl_xor_sync(0xffffffffu, s0, 1);
    s0 += __shfl_xor_sync(0xffffffffu, s0, 2);
    s1 += __shfl_xor_sync(0xffffffffu, s1, 1);
    s1 += __shfl_xor_sync(0xffffffffu, s1, 2);
    if (tig == 0) { red[g * 16 + wid] = s0; red[(g + 8) * 16 + wid] = s1; }
    __syncthreads();
    float t0 = 0.f, t1 = 0.f;
    #pragma unroll
    for (int w = 0; w < 16; w++) {
        t0 += red[g * 16 + w];
        t1 += red[(g + 8) * 16 + w];
    }
    const float inv0 = __fdividef(1.0f, t0);
    const float inv1 = __fdividef(1.0f, t1);

    float* base0 = attn + (size_t)bh * Sq * Sq + (size_t)(m0 + g) * Sq;
    float* base1 = base0 + (size_t)8 * Sq;
    #pragma unroll
    for (int it = 0; it < 4; it++)
        #pragma unroll
        for (int nt = 0; nt < 2; nt++) {
            const int col = it * 256 + wid * 16 + nt * 8 + tig * 2;
            const float* a4 = acc[it][nt];
            *(float2*)(base0 + col) = make_float2(a4[0] * inv0, a4[1] * inv0);
            *(float2*)(base1 + col) = make_float2(a4[2] * inv1, a4[3] * inv1);
        }
}

// -----------------------------------------------------------------------------
extern "C" void kernel_launch(void* const* d_in, const int* in_sizes, int n_in,
                              void* d_out, int out_size)
{
    (void)in_sizes; (void)n_in; (void)out_size;
    const float* x    = (const float*)d_in[0];
    const float* Wq   = (const float*)d_in[1];
    const float* Wk   = (const float*)d_in[2];
    /* d_in[3] = Wv : dead in the reference */
    const float* ln1s = (const float*)d_in[4];
    const float* ln1b = (const float*)d_in[5];
    const float* ln2s = (const float*)d_in[6];
    const float* ln2b = (const float*)d_in[7];
    const float* ff1w = (const float*)d_in[8];
    const float* ff1b = (const float*)d_in[9];
    const float* ff2w = (const float*)d_in[10];
    const float* ff2b = (const float*)d_in[11];

    float* out  = (float*)d_out;
    float* attn = out + (size_t)NTOK * Dd;

    float* px2;
    __half *phh, *phl, *ph2h, *ph2l, *pf1h, *pf1l, *pqh, *pql, *pkh, *pkl;
    __half *pwq, *pwk, *pw1, *pw2;
    cudaGetSymbolAddress((void**)&px2,  g_x2);
    cudaGetSymbolAddress((void**)&phh,  g_hh);
    cudaGetSymbolAddress((void**)&phl,  g_hl);
    cudaGetSymbolAddress((void**)&ph2h, g_h2h);
    cudaGetSymbolAddress((void**)&ph2l, g_h2l);
    cudaGetSymbolAddress((void**)&pf1h, g_f1h);
    cudaGetSymbolAddress((void**)&pf1l, g_f1l);
    cudaGetSymbolAddress((void**)&pqh,  g_qh);
    cudaGetSymbolAddress((void**)&pql,  g_ql);
    cudaGetSymbolAddress((void**)&pkh,  g_kh);
    cudaGetSymbolAddress((void**)&pkl,  g_kl);
    cudaGetSymbolAddress((void**)&pwq,  g_wq);
    cudaGetSymbolAddress((void**)&pwk,  g_wk);
    cudaGetSymbolAddress((void**)&pw1,  g_w1);
    cudaGetSymbolAddress((void**)&pw2,  g_w2);

    cudaFuncSetAttribute(scores_softmax, cudaFuncAttributeMaxDynamicSharedMemorySize, FS_SMEM);

    // launch 0: fused layernorms
    ln_fused<<<NTOK, 256>>>(x, ln1s, ln1b, ln2s, ln2b);

    // launch 1: all 4 weight converts in one kernel
    CvtArgs ca;
    ca.w[0] = (const float4*)Wq;   ca.o[0] = pwq;
    ca.w[1] = (const float4*)Wk;   ca.o[1] = pwk;
    ca.w[2] = (const float4*)ff1w; ca.o[2] = pw1;
    ca.w[3] = (const float4*)ff2w; ca.o[3] = pw2;
    const int n4 = Dd * Dd / 4;
    dim3 gc((n4 + 255) / 256, 4);
    cvt_all<<<gc, 256>>>(ca, n4);

    // launch 2: batched q+k projection
    dim3 gqk(Dd / 128, NTOK / 128, 2);
    gemm2<3, true><<<gqk, 256>>>(NTOK, Dd, Dd, phh, phl, pwq, pwk,
                                 nullptr, nullptr, nullptr,
                                 pqh, pql, pkh, pkl);

    // launch 3 (ncu-profiled slot): fused scores + softmax
    dim3 gs(Sq / 16, NBH);
    scores_softmax<<<gs, 512, FS_SMEM>>>(pqh, pql, pkh, pkl, attn);

    // launches 4-5: FFN
    dim3 g0(Dd / 128, NTOK / 128);
    gemm2<1, false><<<g0, 256>>>(NTOK, Dd, Dd, ph2h, ph2l, pw1, nullptr,
                                 nullptr, ff1b, nullptr,
                                 pf1h, pf1l, nullptr, nullptr);
    gemm2<2, false><<<g0, 256>>>(NTOK, Dd, Dd, pf1h, pf1l, pw2, nullptr,
                                 out, ff2b, px2,
                                 nullptr, nullptr, nullptr, nullptr);
}